// round 13
// baseline (speedup 1.0000x reference)
#include <cuda_runtime.h>
#include <math.h>

#define BB 64
#define QQ 300
#define NN 64
#define CC 6
#define KK 10          // ceil(QQ/32) columns per lane
#define EPSF 1e-6f
#define THREADS 256
#define RCAP 256       // max parallel-ARR rounds
#define QMSK 127       // circular queue (capacity 128 >= max 64 outstanding)

// Scratch (no cudaMalloc allowed).
__device__ double   g_partial[BB][5];
__device__ unsigned g_done;     // zero-init; reset by last block each launch

// Monotone float<->uint map (order preserved under unsigned compare).
__device__ __forceinline__ unsigned fmap(float f)
{
    unsigned b = __float_as_uint(f);
    return b ^ ((unsigned)((int)b >> 31) | 0x80000000u);
}
__device__ __forceinline__ float funmap(unsigned m)
{
    unsigned b = m ^ ((m & 0x80000000u) ? 0x80000000u : 0xFFFFFFFFu);
    return __uint_as_float(b);
}

__device__ __forceinline__ double warp_sum(double v)
{
    #pragma unroll
    for (int off = 16; off; off >>= 1) v += __shfl_down_sync(0xffffffffu, v, off);
    return v;
}

// ---------------------------------------------------------------------------
// One block per batch. Cost tile in dynamic SMEM. Regret-ordered greedy init,
// parallel (8-warp) ARR with best-bidder conflict resolution, SAP fallback.
// ---------------------------------------------------------------------------
__global__ void __launch_bounds__(THREADS, 1)
fused_kernel(const float* __restrict__ exists,
             const float* __restrict__ coords,
             const float* __restrict__ width,
             const float* __restrict__ ef,
             const float* __restrict__ tracks,
             float* __restrict__ out)
{
    const int b    = blockIdx.x;
    const int tid  = threadIdx.x;
    const int wid  = tid >> 5;
    const int lane = tid & 31;

    extern __shared__ float sCost[];            // [NN][QQ] = 76800 B
    __shared__ float sLse[QQ], sPe[QQ], sCex[QQ];
    __shared__ float sCoord[QQ * 4], sWidth[QQ];
    __shared__ float sEf[QQ * CC];
    __shared__ float sV[QQ];
    __shared__ float sU[NN], sEntry[NN];
    __shared__ float sRowMin[NN], sRegret[NN];
    __shared__ int   sRowArg[NN], sOrder[NN];
    __shared__ int   sPath[QQ], sRow4Col[QQ], sCol4Row[NN];
    __shared__ int   sQueue[128], sLeft[NN];
    __shared__ int   sHead, sTail, sNL;
    __shared__ int   sCi[8], sCj[8];
    __shared__ float sCu1[8], sCu2[8];
    __shared__ int   sLast;
    __shared__ double sRed[8][5];

    // ---- Phase A: stage per-q data ----
    for (int q = tid; q < QQ; q += THREADS) {
        int bq = b * QQ + q;
        const float* e = ef + (size_t)bq * CC;
        float e0 = e[0], e1 = e[1], e2 = e[2], e3 = e[3], e4 = e[4], e5 = e[5];
        sEf[q * CC + 0] = e0; sEf[q * CC + 1] = e1; sEf[q * CC + 2] = e2;
        sEf[q * CC + 3] = e3; sEf[q * CC + 4] = e4; sEf[q * CC + 5] = e5;
        float mx = fmaxf(fmaxf(fmaxf(e0, e1), fmaxf(e2, e3)), fmaxf(e4, e5));
        float s = expf(e0 - mx) + expf(e1 - mx) + expf(e2 - mx)
                + expf(e3 - mx) + expf(e4 - mx) + expf(e5 - mx);
        sLse[q] = mx + logf(s);

        float pe = fminf(fmaxf(exists[bq], EPSF), 1.0f - EPSF);
        sPe[q]  = pe;
        sCex[q] = -logf(pe + 1e-8f);

        const float* co = coords + (size_t)bq * 4;
        sCoord[q * 4 + 0] = co[0]; sCoord[q * 4 + 1] = co[1];
        sCoord[q * 4 + 2] = co[2]; sCoord[q * 4 + 3] = co[3];
        sWidth[q] = width[bq];

        sRow4Col[q] = -1;
        sV[q] = 0.0f;
    }
    if (tid < NN) sCol4Row[tid] = -1;
    __syncthreads();

    // ---- Phase B: cost tile + per-row min1/min2/argmin (warp per row) ----
    for (int m = 0; m < NN / 8; m++) {
        int i = wid + 8 * m;
        const float* g = tracks + (size_t)(b * NN + i) * 6;
        float g0 = g[0], g1 = g[1], g2 = g[2], g3 = g[3], g4 = g[4];
        int   cls = (int)g[5];

        float    m1 = INFINITY, m2 = INFINITY;
        unsigned jloc = 0x7fffffffu;
        #pragma unroll
        for (int k = 0; k < KK; k++) {
            int j = lane + 32 * k;
            if (j < QQ) {
                float cc = fabsf(sCoord[j * 4 + 0] - g0) + fabsf(sCoord[j * 4 + 1] - g1)
                         + fabsf(sCoord[j * 4 + 2] - g2) + fabsf(sCoord[j * 4 + 3] - g3);
                float cw  = fabsf(sWidth[j] - g4);
                float cef = sLse[j] - sEf[j * CC + cls];
                float c   = 5.0f * cc + 2.0f * cw + 2.0f * cef + 2.0f * sCex[j];
                sCost[i * QQ + j] = c;
                if (c < m1) { m2 = m1; m1 = c; jloc = (unsigned)j; }
                else if (c < m2) { m2 = c; }
            }
        }
        unsigned mb  = fmap(m1);
        unsigned gm1 = __reduce_min_sync(0xffffffffu, mb);
        unsigned jc  = (mb == gm1) ? jloc : 0x7fffffffu;
        unsigned bj  = __reduce_min_sync(0xffffffffu, jc);
        float    x   = (jc == bj) ? m2 : m1;
        unsigned gm2 = __reduce_min_sync(0xffffffffu, fmap(x));
        if (lane == 0) {
            sRowMin[i] = funmap(gm1);
            sRowArg[i] = (int)bj;
            sRegret[i] = funmap(gm2) - funmap(gm1);
        }
    }
    __syncthreads();
    if (tid < NN) sU[tid] = sRowMin[tid];

    // Rank rows by descending regret (deterministic; ties -> lower row first).
    if (tid < NN) {
        float r = sRegret[tid];
        int rank = 0;
        for (int k = 0; k < NN; k++) {
            float rk = sRegret[k];
            if (rk > r || (rk == r && k < tid)) rank++;
        }
        sOrder[rank] = tid;
    }
    __syncthreads();

    // Greedy init (tid 0) in regret order: row -> argmin column if free.
    if (tid == 0) {
        int t = 0;
        for (int o = 0; o < NN; o++) {
            int i = sOrder[o];
            int j = sRowArg[i];
            if (sRow4Col[j] < 0) { sRow4Col[j] = i; sCol4Row[i] = j; }
            else                 sQueue[t++] = i;
        }
        sHead = 0; sTail = t; sNL = 0;
    }
    __syncthreads();

    unsigned invalid = 0;
    #pragma unroll
    for (int k = 0; k < KK; k++)
        if (lane + 32 * k >= QQ) invalid |= 1u << k;

    // ---- Phase C1: parallel ARR, best-bidder conflict resolution ----
    int rounds = 0;
    while (rounds < RCAP) {
        int head = sHead, tail = sTail;
        if (head >= tail) break;
        int navail = tail - head; if (navail > 8) navail = 8;

        if (wid < navail) {
            int i = sQueue[(head + wid) & QMSK];
            const float* crow = sCost + i * QQ;

            float    m1 = INFINITY, m2 = INFINITY;
            unsigned jloc = 0x7fffffffu;
            #pragma unroll
            for (int k = 0; k < KK; k++) {
                if (!((invalid >> k) & 1u)) {
                    int   j = lane + 32 * k;
                    float d = crow[j] - sV[j];
                    if (d < m1) { m2 = m1; m1 = d; jloc = (unsigned)j; }
                    else if (d < m2) { m2 = d; }
                }
            }
            unsigned mb  = fmap(m1);
            unsigned gm1 = __reduce_min_sync(0xffffffffu, mb);
            unsigned jc  = (mb == gm1) ? jloc : 0x7fffffffu;
            unsigned j1  = __reduce_min_sync(0xffffffffu, jc);
            float    x   = (jc == j1) ? m2 : m1;
            unsigned gm2 = __reduce_min_sync(0xffffffffu, fmap(x));
            if (lane == 0) {
                sCi[wid] = i; sCj[wid] = (int)j1;
                sCu1[wid] = funmap(gm1); sCu2[wid] = funmap(gm2);
            }
        }
        __syncthreads();

        if (tid == 0) {
            int newtail = tail;
            bool done[8];
            for (int w = 0; w < 8; w++) done[w] = false;
            for (int w = 0; w < navail; w++) {
                if (done[w]) continue;
                int j1 = sCj[w];
                // best bidder for j1 = min u1 (ties -> earliest slot)
                int best = w;
                for (int w2 = w + 1; w2 < navail; w2++)
                    if (!done[w2] && sCj[w2] == j1 && sCu1[w2] < sCu1[best])
                        best = w2;
                // requeue losers of this column
                for (int w2 = w; w2 < navail; w2++) {
                    if (!done[w2] && sCj[w2] == j1 && w2 != best) {
                        done[w2] = true;
                        sQueue[newtail & QMSK] = sCi[w2]; newtail++;
                    }
                }
                done[best] = true;
                int   i  = sCi[best];
                float u1 = sCu1[best], u2 = sCu2[best];
                int owner = sRow4Col[j1];
                if (owner >= 0 && !(u1 < u2)) { sLeft[sNL++] = i; continue; }
                sV[j1] -= (u2 - u1);
                sU[i] = u2;
                sRow4Col[j1] = i;
                sCol4Row[i]  = j1;
                if (owner >= 0) { sCol4Row[owner] = -1; sQueue[newtail & QMSK] = owner; newtail++; }
            }
            sHead = head + navail;
            sTail = newtail;
        }
        __syncthreads();
        rounds++;
    }
    // Flush any remaining queued rows (round cap hit) to SAP.
    if (tid == 0) {
        while (sHead < sTail) { sLeft[sNL++] = sQueue[sHead & QMSK]; sHead++; }
    }
    __syncthreads();

    // ---- Phase C2: shortest augmenting path (warp 0) for leftovers ----
    if (wid == 0) {
        const int nL = sNL;
        for (int f = 0; f < nL; f++) {
            const int cur = sLeft[f];

            float shortest[KK];
            #pragma unroll
            for (int k = 0; k < KK; k++) shortest[k] = INFINITY;
            unsigned sc = invalid;
            for (int r = lane; r < NN; r += 32) sEntry[r] = -INFINITY;
            __syncwarp();

            float minv = 0.0f;
            int   i    = cur;
            int   sink = -1;

            while (sink < 0) {
                float m2s = minv - sU[i];
                const float* crow = sCost + i * QQ;

                float    bestv = INFINITY;
                unsigned bestj = 0x7fffffffu;
                #pragma unroll
                for (int k = 0; k < KK; k++) {
                    if (!((sc >> k) & 1u)) {
                        int   j = lane + 32 * k;
                        float d = (m2s + crow[j]) - sV[j];
                        if (d < shortest[k]) { shortest[k] = d; sPath[j] = i; }
                        float s = shortest[k];
                        if (s < bestv) { bestv = s; bestj = (unsigned)j; }
                    }
                }

                unsigned mb   = fmap(bestv);
                unsigned gmin = __reduce_min_sync(0xffffffffu, mb);
                unsigned jc   = (mb == gmin) ? bestj : 0x7fffffffu;
                unsigned bj   = __reduce_min_sync(0xffffffffu, jc);
                minv = funmap(gmin);

                if ((int)(bj & 31u) == lane) sc |= 1u << (bj >> 5);

                int r = sRow4Col[bj];
                if (r < 0) {
                    sink = (int)bj;
                } else {
                    if (lane == 0) sEntry[r] = minv;
                    i = r;
                }
            }

            __syncwarp();
            if (lane == 0) sU[cur] += minv;
            for (int r = lane; r < NN; r += 32) {
                float e = sEntry[r];
                if (e != -INFINITY && r != cur) sU[r] += minv - e;
            }
            unsigned scn = sc & ~invalid;
            #pragma unroll
            for (int k = 0; k < KK; k++)
                if ((scn >> k) & 1u) sV[lane + 32 * k] -= minv - shortest[k];
            __syncwarp();

            if (lane == 0) {
                int j = sink;
                while (1) {
                    int i2 = sPath[j];
                    sRow4Col[j] = i2;
                    int tt = sCol4Row[i2];
                    sCol4Row[i2] = j;
                    j = tt;
                    if (i2 == cur) break;
                }
            }
            __syncwarp();
        }
    }
    __syncthreads();

    // ---- Phase D: per-batch loss partials ----
    double vc = 0.0, vw = 0.0, ve = 0.0, vx = 0.0, nv = 0.0;

    if (tid < NN) {
        int i = tid;
        int j = sCol4Row[i];
        const float* g = tracks + (size_t)(b * NN + i) * 6;

        vc = (double)(fabsf(sCoord[j * 4 + 0] - g[0]) + fabsf(sCoord[j * 4 + 1] - g[1])
                    + fabsf(sCoord[j * 4 + 2] - g[2]) + fabsf(sCoord[j * 4 + 3] - g[3]));
        vw = (double)fabsf(sWidth[j] - g[4]);

        const float* e = sEf + j * CC;
        float mx = e[0];
        #pragma unroll
        for (int k = 1; k < CC; k++) mx = fmaxf(mx, e[k]);
        float s = 0.0f;
        #pragma unroll
        for (int k = 0; k < CC; k++) s += expf(e[k] - mx);
        int cls = (int)g[5];
        ve = (double)(-(e[cls] - mx - logf(s)));

        vx = (double)(-logf(sPe[j]));
    }

    for (int q = tid; q < QQ; q += THREADS)
        if (sRow4Col[q] < 0) nv += (double)(-logf(1.0f - sPe[q]));

    vc = warp_sum(vc); vw = warp_sum(vw); ve = warp_sum(ve);
    vx = warp_sum(vx); nv = warp_sum(nv);
    if (lane == 0) {
        sRed[wid][0] = vc; sRed[wid][1] = vw; sRed[wid][2] = ve;
        sRed[wid][3] = vx; sRed[wid][4] = nv;
    }
    __syncthreads();

    if (tid == 0) {
        double a0 = 0, a1 = 0, a2 = 0, a3 = 0, a4 = 0;
        #pragma unroll
        for (int w = 0; w < 8; w++) {
            a0 += sRed[w][0]; a1 += sRed[w][1]; a2 += sRed[w][2];
            a3 += sRed[w][3]; a4 += sRed[w][4];
        }
        g_partial[b][0] = a0; g_partial[b][1] = a1; g_partial[b][2] = a2;
        g_partial[b][3] = a3; g_partial[b][4] = a4;
        __threadfence();
        unsigned old = atomicAdd(&g_done, 1u);
        sLast = (old == gridDim.x - 1) ? 1 : 0;
    }
    __syncthreads();

    // ---- Last block: reduce partials, finalize, reset counter ----
    if (sLast && wid == 0) {
        __threadfence();
        double a[5] = {0, 0, 0, 0, 0};
        for (int b2 = lane; b2 < BB; b2 += 32) {
            #pragma unroll
            for (int k = 0; k < 5; k++) a[k] += g_partial[b2][k];
        }
        #pragma unroll
        for (int k = 0; k < 5; k++) a[k] = warp_sum(a[k]);

        if (lane == 0) {
            const double nm = (double)(BB * NN);
            const double nu = (double)(BB * QQ - BB * NN);
            double coord = 5.0 * a[0] / nm;
            double w     = 2.0 * a[1] / nm;
            double e     = 2.0 * a[2] / nm;
            double x     = 2.0 * a[3] / nm;
            double no    = 1.0 * a[4] / nu;
            out[0] = (float)(coord + w + e + x + no);
            out[1] = (float)coord;
            out[2] = (float)w;
            out[3] = (float)e;
            out[4] = (float)x;
            out[5] = (float)no;
            __threadfence();
            g_done = 0u;   // reset for next graph replay
        }
    }
}

// ---------------------------------------------------------------------------
extern "C" void kernel_launch(void* const* d_in, const int* in_sizes, int n_in,
                              void* d_out, int out_size)
{
    const float* exists = (const float*)d_in[0];
    const float* coords = (const float*)d_in[1];
    const float* width  = (const float*)d_in[2];
    const float* ef     = (const float*)d_in[3];
    const float* tracks = (const float*)d_in[4];
    float* out = (float*)d_out;

    const int dyn = NN * QQ * (int)sizeof(float);   // 76800 B
    cudaFuncSetAttribute(fused_kernel,
                         cudaFuncAttributeMaxDynamicSharedMemorySize, dyn);
    fused_kernel<<<BB, THREADS, dyn>>>(exists, coords, width, ef, tracks, out);
}

// round 14
// speedup vs baseline: 1.5982x; 1.5982x over previous
#include <cuda_runtime.h>
#include <math.h>

#define BB 64
#define QQ 300
#define NN 64
#define CC 6
#define KK 10          // ceil(QQ/32) columns per lane
#define EPSF 1e-6f
#define THREADS 256
#define PCAP 4096      // ARR step safety cap (SAP fallback is always correct)
#define QMSK 127       // circular queue (outstanding rows <= 64 < 128)

// Scratch (no cudaMalloc allowed).
__device__ double   g_partial[BB][5];
__device__ unsigned g_done;     // zero-init; reset by last block each launch

// Monotone float<->uint map (order preserved under unsigned compare).
__device__ __forceinline__ unsigned fmap(float f)
{
    unsigned b = __float_as_uint(f);
    return b ^ ((unsigned)((int)b >> 31) | 0x80000000u);
}
__device__ __forceinline__ float funmap(unsigned m)
{
    unsigned b = m ^ ((m & 0x80000000u) ? 0x80000000u : 0xFFFFFFFFu);
    return __uint_as_float(b);
}

__device__ __forceinline__ double warp_sum(double v)
{
    #pragma unroll
    for (int off = 16; off; off >>= 1) v += __shfl_down_sync(0xffffffffu, v, off);
    return v;
}

// ---------------------------------------------------------------------------
// One block per batch. Cost tile in dynamic SMEM. Serial warp-0 ARR with an
// exact per-row top-8 shortlist fast path; full-scan fallback; SAP leftovers.
// ---------------------------------------------------------------------------
__global__ void __launch_bounds__(THREADS, 1)
fused_kernel(const float* __restrict__ exists,
             const float* __restrict__ coords,
             const float* __restrict__ width,
             const float* __restrict__ ef,
             const float* __restrict__ tracks,
             float* __restrict__ out)
{
    const int b    = blockIdx.x;
    const int tid  = threadIdx.x;
    const int wid  = tid >> 5;
    const int lane = tid & 31;

    extern __shared__ float sCost[];            // [NN][QQ] = 76800 B
    __shared__ float sLse[QQ], sPe[QQ], sCex[QQ];
    __shared__ float sCoord[QQ * 4], sWidth[QQ];
    __shared__ float sEf[QQ * CC];
    __shared__ float sV[QQ];
    __shared__ float sU[NN], sEntry[NN];
    __shared__ float sTopC[NN][8];              // 8 smallest costs (ascending)
    __shared__ int   sTopJ[NN][8];
    __shared__ float sBound[NN];                // == sTopC[i][7]
    __shared__ int   sPath[QQ], sRow4Col[QQ], sCol4Row[NN];
    __shared__ int   sQueue[128], sLeft[NN];
    __shared__ int   sTail, sNL;
    __shared__ int   sLast;
    __shared__ double sRed[8][5];

    // ---- Phase A: stage per-q data ----
    for (int q = tid; q < QQ; q += THREADS) {
        int bq = b * QQ + q;
        const float* e = ef + (size_t)bq * CC;
        float e0 = e[0], e1 = e[1], e2 = e[2], e3 = e[3], e4 = e[4], e5 = e[5];
        sEf[q * CC + 0] = e0; sEf[q * CC + 1] = e1; sEf[q * CC + 2] = e2;
        sEf[q * CC + 3] = e3; sEf[q * CC + 4] = e4; sEf[q * CC + 5] = e5;
        float mx = fmaxf(fmaxf(fmaxf(e0, e1), fmaxf(e2, e3)), fmaxf(e4, e5));
        float s = expf(e0 - mx) + expf(e1 - mx) + expf(e2 - mx)
                + expf(e3 - mx) + expf(e4 - mx) + expf(e5 - mx);
        sLse[q] = mx + logf(s);

        float pe = fminf(fmaxf(exists[bq], EPSF), 1.0f - EPSF);
        sPe[q]  = pe;
        sCex[q] = -logf(pe + 1e-8f);

        const float* co = coords + (size_t)bq * 4;
        sCoord[q * 4 + 0] = co[0]; sCoord[q * 4 + 1] = co[1];
        sCoord[q * 4 + 2] = co[2]; sCoord[q * 4 + 3] = co[3];
        sWidth[q] = width[bq];

        sRow4Col[q] = -1;
        sV[q] = 0.0f;
    }
    if (tid < NN) sCol4Row[tid] = -1;
    __syncthreads();

    // ---- Phase B: cost tile + per-row top-8 (value, col) ascending ----
    for (int m = 0; m < NN / 8; m++) {
        int i = wid + 8 * m;
        const float* g = tracks + (size_t)(b * NN + i) * 6;
        float g0 = g[0], g1 = g[1], g2 = g[2], g3 = g[3], g4 = g[4];
        int   cls = (int)g[5];

        float c[KK];
        #pragma unroll
        for (int k = 0; k < KK; k++) {
            int j = lane + 32 * k;
            if (j < QQ) {
                float cc = fabsf(sCoord[j * 4 + 0] - g0) + fabsf(sCoord[j * 4 + 1] - g1)
                         + fabsf(sCoord[j * 4 + 2] - g2) + fabsf(sCoord[j * 4 + 3] - g3);
                float cw  = fabsf(sWidth[j] - g4);
                float cef = sLse[j] - sEf[j * CC + cls];
                float cv  = 5.0f * cc + 2.0f * cw + 2.0f * cef + 2.0f * sCex[j];
                sCost[i * QQ + j] = cv;
                c[k] = cv;
            } else {
                c[k] = INFINITY;
            }
        }
        // Extract 8 smallest (destructive on c[])
        #pragma unroll
        for (int r8 = 0; r8 < 8; r8++) {
            float lm = INFINITY; int lk = 0;
            #pragma unroll
            for (int k = 0; k < KK; k++)
                if (c[k] < lm) { lm = c[k]; lk = k; }
            unsigned mb = fmap(lm);
            unsigned g8 = __reduce_min_sync(0xffffffffu, mb);
            unsigned jc = (mb == g8) ? (unsigned)(lane + 32 * lk) : 0x7fffffffu;
            unsigned bj = __reduce_min_sync(0xffffffffu, jc);
            if (lane == (int)(bj & 31u)) c[bj >> 5] = INFINITY;
            if (lane == 0) { sTopJ[i][r8] = (int)bj; sTopC[i][r8] = funmap(g8); }
        }
        if (lane == 0) sBound[i] = sTopC[i][7];
    }
    __syncthreads();
    if (tid < NN) sU[tid] = sTopC[tid][0];

    // Greedy init (tid 0): row -> argmin column if free; else queue (FIFO).
    if (tid == 0) {
        int t = 0;
        for (int i = 0; i < NN; i++) {
            int j = sTopJ[i][0];
            if (sRow4Col[j] < 0) { sRow4Col[j] = i; sCol4Row[i] = j; }
            else                 sQueue[t++] = i;
        }
        sTail = t; sNL = 0;
    }
    __syncthreads();

    unsigned invalid = 0;
    #pragma unroll
    for (int k = 0; k < KK; k++)
        if (lane + 32 * k >= QQ) invalid |= 1u << k;

    // ---- Phase C1: serial ARR on warp 0, top-8 fast path ----
    if (wid == 0) {
        int h = 0, t = sTail, nL = 0, processed = 0;
        while (h < t && processed < PCAP) {
            processed++;
            const int i = sQueue[h & QMSK]; h++;

            // Fast path: evaluate the 8 stored candidates at current v.
            float d  = INFINITY;
            int   jj = 0x7fffffff;
            if (lane < 8) { jj = sTopJ[i][lane]; d = sTopC[i][lane] - sV[jj]; }
            unsigned mb  = fmap(d);
            unsigned gm1 = __reduce_min_sync(0xffffffffu, mb);
            unsigned jc  = (mb == gm1) ? (unsigned)jj : 0x7fffffffu;
            unsigned bj  = __reduce_min_sync(0xffffffffu, jc);
            float    x   = (jj == (int)bj) ? INFINITY : d;
            unsigned gm2 = __reduce_min_sync(0xffffffffu, fmap(x));
            float m1 = funmap(gm1);
            float m2 = funmap(gm2);
            int  j1  = (int)bj;

            const float bound = sBound[i];
            if (!(m1 < bound && m2 < bound)) {
                // Full scan fallback (exact, incl. ties -> lowest j).
                const float* crow = sCost + i * QQ;
                float    f1 = INFINITY, f2 = INFINITY;
                unsigned jloc = 0x7fffffffu;
                #pragma unroll
                for (int k = 0; k < KK; k++) {
                    if (!((invalid >> k) & 1u)) {
                        int   j = lane + 32 * k;
                        float dd = crow[j] - sV[j];
                        if (dd < f1) { f2 = f1; f1 = dd; jloc = (unsigned)j; }
                        else if (dd < f2) { f2 = dd; }
                    }
                }
                unsigned fb  = fmap(f1);
                unsigned fg1 = __reduce_min_sync(0xffffffffu, fb);
                unsigned fjc = (fb == fg1) ? jloc : 0x7fffffffu;
                unsigned fbj = __reduce_min_sync(0xffffffffu, fjc);
                float    fx  = (fjc == fbj) ? f2 : f1;
                unsigned fg2 = __reduce_min_sync(0xffffffffu, fmap(fx));
                m1 = funmap(fg1);
                m2 = funmap(fg2);
                j1 = (int)fbj;
            }

            int owner = sRow4Col[j1];
            if (owner >= 0 && !(m1 < m2)) {
                if (lane == 0) sLeft[nL] = i;     // tie: defer to SAP
                nL++;
                __syncwarp();
                continue;
            }

            if (lane == 0) {
                sV[j1] -= (m2 - m1);
                sU[i] = m2;
                sRow4Col[j1] = i;
                sCol4Row[i]  = j1;
                if (owner >= 0) { sCol4Row[owner] = -1; sQueue[t & QMSK] = owner; }
            }
            if (owner >= 0) t++;
            __syncwarp();
        }
        // Flush anything unprocessed (cap hit) to SAP.
        while (h < t) {
            if (lane == 0) sLeft[nL] = sQueue[h & QMSK];
            nL++; h++;
        }
        if (lane == 0) sNL = nL;
        __syncwarp();

        // ---- Phase C2: shortest augmenting path for leftovers ----
        const int NL = nL;
        for (int f = 0; f < NL; f++) {
            const int cur = sLeft[f];

            float shortest[KK];
            #pragma unroll
            for (int k = 0; k < KK; k++) shortest[k] = INFINITY;
            unsigned sc = invalid;
            for (int r = lane; r < NN; r += 32) sEntry[r] = -INFINITY;
            __syncwarp();

            float minv = 0.0f;
            int   i    = cur;
            int   sink = -1;

            while (sink < 0) {
                float m2s = minv - sU[i];
                const float* crow = sCost + i * QQ;

                float    bestv = INFINITY;
                unsigned bestj = 0x7fffffffu;
                #pragma unroll
                for (int k = 0; k < KK; k++) {
                    if (!((sc >> k) & 1u)) {
                        int   j = lane + 32 * k;
                        float d = (m2s + crow[j]) - sV[j];
                        if (d < shortest[k]) { shortest[k] = d; sPath[j] = i; }
                        float s = shortest[k];
                        if (s < bestv) { bestv = s; bestj = (unsigned)j; }
                    }
                }

                unsigned mb   = fmap(bestv);
                unsigned gmin = __reduce_min_sync(0xffffffffu, mb);
                unsigned jc   = (mb == gmin) ? bestj : 0x7fffffffu;
                unsigned bj   = __reduce_min_sync(0xffffffffu, jc);
                minv = funmap(gmin);

                if ((int)(bj & 31u) == lane) sc |= 1u << (bj >> 5);

                int r = sRow4Col[bj];
                if (r < 0) {
                    sink = (int)bj;
                } else {
                    if (lane == 0) sEntry[r] = minv;
                    i = r;
                }
            }

            __syncwarp();
            if (lane == 0) sU[cur] += minv;
            for (int r = lane; r < NN; r += 32) {
                float e = sEntry[r];
                if (e != -INFINITY && r != cur) sU[r] += minv - e;
            }
            unsigned scn = sc & ~invalid;
            #pragma unroll
            for (int k = 0; k < KK; k++)
                if ((scn >> k) & 1u) sV[lane + 32 * k] -= minv - shortest[k];
            __syncwarp();

            if (lane == 0) {
                int j = sink;
                while (1) {
                    int i2 = sPath[j];
                    sRow4Col[j] = i2;
                    int tt = sCol4Row[i2];
                    sCol4Row[i2] = j;
                    j = tt;
                    if (i2 == cur) break;
                }
            }
            __syncwarp();
        }
    }
    __syncthreads();

    // ---- Phase D: per-batch loss partials ----
    double vc = 0.0, vw = 0.0, ve = 0.0, vx = 0.0, nv = 0.0;

    if (tid < NN) {
        int i = tid;
        int j = sCol4Row[i];
        const float* g = tracks + (size_t)(b * NN + i) * 6;

        vc = (double)(fabsf(sCoord[j * 4 + 0] - g[0]) + fabsf(sCoord[j * 4 + 1] - g[1])
                    + fabsf(sCoord[j * 4 + 2] - g[2]) + fabsf(sCoord[j * 4 + 3] - g[3]));
        vw = (double)fabsf(sWidth[j] - g[4]);

        const float* e = sEf + j * CC;
        float mx = e[0];
        #pragma unroll
        for (int k = 1; k < CC; k++) mx = fmaxf(mx, e[k]);
        float s = 0.0f;
        #pragma unroll
        for (int k = 0; k < CC; k++) s += expf(e[k] - mx);
        int cls = (int)g[5];
        ve = (double)(-(e[cls] - mx - logf(s)));

        vx = (double)(-logf(sPe[j]));
    }

    for (int q = tid; q < QQ; q += THREADS)
        if (sRow4Col[q] < 0) nv += (double)(-logf(1.0f - sPe[q]));

    vc = warp_sum(vc); vw = warp_sum(vw); ve = warp_sum(ve);
    vx = warp_sum(vx); nv = warp_sum(nv);
    if (lane == 0) {
        sRed[wid][0] = vc; sRed[wid][1] = vw; sRed[wid][2] = ve;
        sRed[wid][3] = vx; sRed[wid][4] = nv;
    }
    __syncthreads();

    if (tid == 0) {
        double a0 = 0, a1 = 0, a2 = 0, a3 = 0, a4 = 0;
        #pragma unroll
        for (int w = 0; w < 8; w++) {
            a0 += sRed[w][0]; a1 += sRed[w][1]; a2 += sRed[w][2];
            a3 += sRed[w][3]; a4 += sRed[w][4];
        }
        g_partial[b][0] = a0; g_partial[b][1] = a1; g_partial[b][2] = a2;
        g_partial[b][3] = a3; g_partial[b][4] = a4;
        __threadfence();
        unsigned old = atomicAdd(&g_done, 1u);
        sLast = (old == gridDim.x - 1) ? 1 : 0;
    }
    __syncthreads();

    // ---- Last block: reduce partials, finalize, reset counter ----
    if (sLast && wid == 0) {
        __threadfence();
        double a[5] = {0, 0, 0, 0, 0};
        for (int b2 = lane; b2 < BB; b2 += 32) {
            #pragma unroll
            for (int k = 0; k < 5; k++) a[k] += g_partial[b2][k];
        }
        #pragma unroll
        for (int k = 0; k < 5; k++) a[k] = warp_sum(a[k]);

        if (lane == 0) {
            const double nm = (double)(BB * NN);
            const double nu = (double)(BB * QQ - BB * NN);
            double coord = 5.0 * a[0] / nm;
            double w     = 2.0 * a[1] / nm;
            double e     = 2.0 * a[2] / nm;
            double x     = 2.0 * a[3] / nm;
            double no    = 1.0 * a[4] / nu;
            out[0] = (float)(coord + w + e + x + no);
            out[1] = (float)coord;
            out[2] = (float)w;
            out[3] = (float)e;
            out[4] = (float)x;
            out[5] = (float)no;
            __threadfence();
            g_done = 0u;   // reset for next graph replay
        }
    }
}

// ---------------------------------------------------------------------------
extern "C" void kernel_launch(void* const* d_in, const int* in_sizes, int n_in,
                              void* d_out, int out_size)
{
    const float* exists = (const float*)d_in[0];
    const float* coords = (const float*)d_in[1];
    const float* width  = (const float*)d_in[2];
    const float* ef     = (const float*)d_in[3];
    const float* tracks = (const float*)d_in[4];
    float* out = (float*)d_out;

    const int dyn = NN * QQ * (int)sizeof(float);   // 76800 B
    cudaFuncSetAttribute(fused_kernel,
                         cudaFuncAttributeMaxDynamicSharedMemorySize, dyn);
    fused_kernel<<<BB, THREADS, dyn>>>(exists, coords, width, ef, tracks, out);
}